// round 15
// baseline (speedup 1.0000x reference)
#include <cuda_runtime.h>
#include <cuda_bf16.h>
#include <cstdint>

// B=8, N=2048, FEAT=16, pos = feats [0,2), radius = 0.25.
// Output [B, N, N] fp32 mask = 128 MiB stores; store-path acceptance is the
// wall (R12 main kernel: 23.8us). Single launch removes the 4.9us
// compact+launch-gap overhead; 256 blocks keeps the strided position
// prologue at 16MB grid-wide (64KB sectors per block), matching the dense
// two-kernel read budget. Geometry FIXED vs R14: 32 blocks/batch, 64 rows.
static constexpr int N_     = 2048;
static constexpr int BATCH_ = 8;
static constexpr int R_ROWS = 64;          // rows per block -> 32 blocks/batch
static constexpr float R2   = 0.0625f;     // 0.25^2

__device__ __forceinline__ int read_idx_arr(const int* __restrict__ a32, int b)
{
    // Handles both int32 and int64(small values) materialization of T/taus.
    const bool is64 = (a32[1] == 0) && (a32[0] != 0);
    return is64 ? a32[2 * b] : a32[b];
}

__global__ void __launch_bounds__(512, 2)
radius_edge_kernel(const float* __restrict__ nodes,
                   const int* __restrict__ T_arr,
                   const int* __restrict__ tau_arr,
                   float4* __restrict__ out)
{
    // grid = BATCH_ * (N_/R_ROWS) = 8 * 32 = 256 blocks x 512 threads.
    const int b  = blockIdx.x >> 5;            // /32  (32 blocks per batch)
    const int i0 = (blockIdx.x & 31) * R_ROWS; // rows [i0, i0+64)
    const int t  = threadIdx.x;                // one float4 column-group each

    const int Tlo = read_idx_arr(T_arr, b);
    const int Thi = Tlo + read_idx_arr(tau_arr, b);  // active cols [Tlo, Thi)

    const int j0 = 4 * t;
    const float* __restrict__ nb = nodes + (size_t)b * N_ * 16;

    // Prologue: read this thread's 4 column positions once (4 x 32B sectors,
    // 64KB per block, 16MB grid-wide; sectors stay L1-hot for the row loop).
    float px[4], py[4];
    #pragma unroll
    for (int k = 0; k < 4; k++) {
        const float2 p = __ldg((const float2*)(nb + (size_t)(j0 + k) * 16));
        px[k] = p.x;
        py[k] = p.y;
    }

    // Loop-invariant column-window mask.
    bool w[4];
    #pragma unroll
    for (int k = 0; k < 4; k++)
        w[k] = (j0 + k >= Tlo) && (j0 + k < Thi);

    float4* orow = out + ((size_t)b * N_ + i0) * (N_ / 4) + t;

    #pragma unroll 4
    for (int r = 0; r < R_ROWS; r++) {
        const int i = i0 + r;
        // Uniform broadcast; sector already touched in prologue -> L1 hit.
        const float2 pi = __ldg((const float2*)(nb + (size_t)i * 16));

        float4 v;
        #pragma unroll
        for (int k = 0; k < 4; k++) {
            const float dx = pi.x - px[k];
            const float dy = pi.y - py[k];
            const bool  c  = w[k] & (i < j0 + k) & (fmaf(dx, dx, dy * dy) < R2);
            (&v.x)[k] = c ? 1.0f : 0.0f;
        }
        orow[(size_t)r * (N_ / 4)] = v;   // coalesced STG.128, interleaved w/ FMA
    }
}

extern "C" void kernel_launch(void* const* d_in, const int* in_sizes, int n_in,
                              void* d_out, int out_size)
{
    const float* nodes   = (const float*)d_in[0];
    const int*   T_arr   = (const int*)d_in[1];
    const int*   tau_arr = (const int*)d_in[2];
    // d_in[3] = B scalar, unused (compile-time constants)

    const int blocks = BATCH_ * (N_ / R_ROWS);   // 8 * 32 = 256
    radius_edge_kernel<<<blocks, 512>>>(nodes, T_arr, tau_arr, (float4*)d_out);
}

// round 16
// speedup vs baseline: 1.0667x; 1.0667x over previous
#include <cuda_runtime.h>
#include <cuda_bf16.h>
#include <cstdint>

// B=8, N=2048, FEAT=16, pos = feats [0,2), radius = 0.25.
// Output [B, N, N] fp32 mask = 128 MiB stores; store-path acceptance pins the
// main kernel at 23.84us (reproduced 3x). Remaining slack is the ~4.9us
// compact+launch gap -> attacked with PDL: compact signals
// griddepcontrol.launch_dependents after its g_pos stores; main kernel is
// launched with programmatic stream serialization and waits
// (griddepcontrol.wait) only before its first g_pos read.
static constexpr int N_     = 2048;
static constexpr int BATCH_ = 8;
static constexpr int R_ROWS = 32;          // rows per block (main kernel)
static constexpr float R2   = 0.0625f;     // 0.25^2

__device__ __align__(16) float2 g_pos[BATCH_][N_];

__device__ __forceinline__ int read_idx_arr(const int* __restrict__ a32, int b)
{
    // Handles both int32 and int64(small values) materialization of T/taus.
    const bool is64 = (a32[1] == 0) && (a32[0] != 0);
    return is64 ? a32[2 * b] : a32[b];
}

__global__ void __launch_bounds__(128)
compact_kernel(const float* __restrict__ nodes)
{
    const int node = blockIdx.x * 128 + threadIdx.x;   // 128 blocks x 128 = 16384
    const float2 p = *(const float2*)(nodes + (size_t)node * 16);
    reinterpret_cast<float2*>(g_pos)[node] = p;        // coalesced 8B store
    // Writes above become visible to the dependent grid's griddepcontrol.wait.
    asm volatile("griddepcontrol.launch_dependents;" ::: "memory");
}

__global__ void __launch_bounds__(256)
radius_edge_kernel(const int* __restrict__ T_arr,
                   const int* __restrict__ tau_arr,
                   float4* __restrict__ out)
{
    // grid = B * (N / R_ROWS) = 8 * 64 = 512 blocks x 256 threads.
    const int b  = blockIdx.x >> 6;            // /64
    const int i0 = (blockIdx.x & 63) * R_ROWS;
    const int t  = threadIdx.x;                // two float4 column-groups each

    const int Tlo = read_idx_arr(T_arr, b);
    const int Thi = Tlo + read_idx_arr(tau_arr, b);  // active cols [Tlo, Thi)

    const int j0a = 4 * t;
    const int j0b = 4 * (t + 256);

    // Loop-invariant window masks (independent of g_pos -> before the wait).
    bool wa[4], wb[4];
    #pragma unroll
    for (int k = 0; k < 4; k++) {
        wa[k] = (j0a + k >= Tlo) && (j0a + k < Thi);
        wb[k] = (j0b + k >= Tlo) && (j0b + k < Thi);
    }

    // Wait for compact_kernel's g_pos stores (PDL handoff).
    asm volatile("griddepcontrol.wait;" ::: "memory");

    // Load the 8 column positions ONCE (4 coalesced LDG.128 from dense g_pos),
    // reuse across all 32 rows.
    const float4* pbase = reinterpret_cast<const float4*>(&g_pos[b][0]);
    const float4 ra0 = pbase[2 * t];
    const float4 ra1 = pbase[2 * t + 1];
    const float4 rb0 = pbase[2 * (t + 256)];
    const float4 rb1 = pbase[2 * (t + 256) + 1];

    const float pax[4] = {ra0.x, ra0.z, ra1.x, ra1.z};
    const float pay[4] = {ra0.y, ra0.w, ra1.y, ra1.w};
    const float pbx[4] = {rb0.x, rb0.z, rb1.x, rb1.z};
    const float pby[4] = {rb0.y, rb0.w, rb1.y, rb1.w};

    float4* orow = out + ((size_t)b * N_ + i0) * (N_ / 4);

    #pragma unroll 4
    for (int r = 0; r < R_ROWS; r++) {
        const int i = i0 + r;
        const float2 pi = g_pos[b][i];   // uniform -> broadcast load (L1 hit)

        float4 va, vb;
        #pragma unroll
        for (int k = 0; k < 4; k++) {
            float dx = pi.x - pax[k];
            float dy = pi.y - pay[k];
            bool  c  = wa[k] & (i < j0a + k) & (fmaf(dx, dx, dy * dy) < R2);
            (&va.x)[k] = c ? 1.0f : 0.0f;

            dx = pi.x - pbx[k];
            dy = pi.y - pby[k];
            c  = wb[k] & (i < j0b + k) & (fmaf(dx, dx, dy * dy) < R2);
            (&vb.x)[k] = c ? 1.0f : 0.0f;
        }

        orow[(size_t)r * (N_ / 4) + t]       = va;   // coalesced STG.128
        orow[(size_t)r * (N_ / 4) + t + 256] = vb;
    }
}

extern "C" void kernel_launch(void* const* d_in, const int* in_sizes, int n_in,
                              void* d_out, int out_size)
{
    const float* nodes   = (const float*)d_in[0];
    const int*   T_arr   = (const int*)d_in[1];
    const int*   tau_arr = (const int*)d_in[2];
    // d_in[3] = B scalar, unused (compile-time constants)

    compact_kernel<<<128, 128>>>(nodes);         // 16384 nodes, 1 thread each

    // Main kernel with programmatic dependent launch: overlaps its launch
    // latency with compact_kernel execution; correctness held by
    // griddepcontrol.wait before the first g_pos read.
    cudaLaunchAttribute attrs[1];
    attrs[0].id = cudaLaunchAttributeProgrammaticStreamSerialization;
    attrs[0].val.programmaticStreamSerializationAllowed = 1;

    cudaLaunchConfig_t cfg = {};
    cfg.gridDim  = dim3(BATCH_ * (N_ / R_ROWS), 1, 1);   // 512
    cfg.blockDim = dim3(256, 1, 1);
    cfg.dynamicSmemBytes = 0;
    cfg.stream = 0;               // same (legacy default) stream as compact
    cfg.attrs = attrs;
    cfg.numAttrs = 1;

    cudaLaunchKernelEx(&cfg, radius_edge_kernel, T_arr, tau_arr, (float4*)d_out);
}